// round 14
// baseline (speedup 1.0000x reference)
#include <cuda_runtime.h>
#include <cuda_fp16.h>
#include <cstdint>

#define N_E   200000
#define N_T   1000000
#define N_R   200
#define N_W2V 300
#define BB    64        // batch
#define STRIP 8         // triples per thread-strip

// Heterogeneous-grid split for the fused pre-hop kernel.
#define TB_TILES   ((N_E + 31) / 32)            // 6250 transpose blocks
#define CNT_BLKS   ((N_T / 4 + 255) / 256)      // 977 histogram blocks
#define CR_BLKS    ((3 * N_R + 7) / 8)          // 75 compute_r blocks (8 warps)
#define FUSEA_BLKS (TB_TILES + CNT_BLKS + CR_BLKS)

// fp16 gather-side state: (N_E, 64) halves, 128B rows. 25.6 MB.
__device__ __align__(256) __half g_x16[(size_t)N_E * BB];
// fp32 accumulator state: (N_E, 64) floats, 256B rows. 51.2 MB. Pre-zeroed.
__device__ __align__(256) float  g_y32[(size_t)N_E * BB];
// Precomputed r for all 3 hops, relation-major fp16: rt[h][j][b]
__device__ __align__(256) __half g_rt16[3][N_R * BB];

// CSR-sort scratch, rebuilt every call.
#define SCAN_BLOCK 2048
#define SCAN_NBLK  ((N_E + SCAN_BLOCK - 1) / SCAN_BLOCK)   // 98
__device__ unsigned g_hist[N_E];
__device__ unsigned g_cursor[N_E];
__device__ unsigned g_bsum[SCAN_NBLK];
__device__ unsigned g_boff[SCAN_NBLK];
// Sorted-by-obj triple stream: .x = (subj<<8)|rel (26 bits), .y = obj. 8 MB.
__device__ __align__(16) uint2 g_sp[N_T];

struct __align__(8) h4 { __half2 a, b; };   // 4 halves = 8 bytes

// ---------------------------------------------------------------------------
// Tiny: zero the histogram (must precede fusedA's count atomics).
// ---------------------------------------------------------------------------
__global__ void csr_zero_hist() {
    const int i = blockIdx.x * blockDim.x + threadIdx.x;
    if (i < N_E) g_hist[i] = 0u;
}

// ---------------------------------------------------------------------------
// Fused pre-hop kernel, heterogeneous grid:
//   blocks [0, TB_TILES):         transpose x -> g_x16 (fp16) + zero g_y32
//   blocks [TB_TILES, +CNT_BLKS): histogram of obj (int4 loads, 4 reds/thread)
//   blocks [.., +CR_BLKS):        compute_r, one warp per (h, j)
// All three jobs are independent; the SMs interleave them, hiding the
// latency-bound histogram behind the bandwidth-bound transpose.
// ---------------------------------------------------------------------------
__global__ void __launch_bounds__(256)
fusedA(const float* __restrict__ x,  const float* __restrict__ q,
       const float* __restrict__ W1, const float* __restrict__ b1,
       const float* __restrict__ W2, const float* __restrict__ b2,
       const float* __restrict__ W3, const float* __restrict__ b3,
       const int* __restrict__ obj) {
    __shared__ float tile[32][BB + 1];
    const int tid  = threadIdx.x;
    const int lane = tid & 31;
    const int warp = tid >> 5;

    if (blockIdx.x < TB_TILES) {
        // ---- transpose + zero ----------------------------------------------
        const int e0 = blockIdx.x * 32;
        for (int b = warp; b < BB; b += 8) {
            const int e = e0 + lane;
            tile[lane][b] = (e < N_E) ? x[(size_t)b * N_E + e] : 0.f;
        }
        {   // zero my slice of g_y32 while tile loads are in flight
            float4* __restrict__ y4 = reinterpret_cast<float4*>(g_y32);
            const size_t base = (size_t)blockIdx.x * 512 + tid;
            const float4 z = make_float4(0.f, 0.f, 0.f, 0.f);
            y4[base]       = z;
            y4[base + 256] = z;
        }
        __syncthreads();
        const int l16 = tid & 15;
        for (int er = tid >> 4; er < 32; er += 16) {
            const int e = e0 + er;
            if (e < N_E) {
                h4 v;
                v.a = __floats2half2_rn(tile[er][l16 * 4 + 0], tile[er][l16 * 4 + 1]);
                v.b = __floats2half2_rn(tile[er][l16 * 4 + 2], tile[er][l16 * 4 + 3]);
                reinterpret_cast<h4*>(g_x16 + (size_t)e * BB)[l16] = v;
            }
        }
    } else if (blockIdx.x < TB_TILES + CNT_BLKS) {
        // ---- histogram: 4 triples per thread, fire-and-forget adds ----------
        const int i  = (blockIdx.x - TB_TILES) * 256 + tid;
        const int t0 = i * 4;
        if (t0 < N_T) {
            const int4 o4 = __ldg(reinterpret_cast<const int4*>(obj + t0));
            atomicAdd(&g_hist[o4.x], 1u);
            atomicAdd(&g_hist[o4.y], 1u);
            atomicAdd(&g_hist[o4.z], 1u);
            atomicAdd(&g_hist[o4.w], 1u);
        }
    } else {
        // ---- compute_r: one warp per (h, j), 600 units ----------------------
        const int w = (blockIdx.x - TB_TILES - CNT_BLKS) * 8 + warp;
        if (w < 3 * N_R) {
            const int h = w / N_R;
            const int j = w - h * N_R;
            const float* __restrict__ W  = (h == 0) ? W1 : (h == 1) ? W2 : W3;
            const float* __restrict__ bv = (h == 0) ? b1 : (h == 1) ? b2 : b3;
            float a0 = bv[j], a1 = a0;
            const float* __restrict__ q0 = q + (size_t)lane * N_W2V;
            const float* __restrict__ q1 = q + (size_t)(lane + 32) * N_W2V;
#pragma unroll 4
            for (int k = 0; k < N_W2V; ++k) {
                const float wk = __ldg(W + (size_t)k * N_R + j);  // warp-broadcast
                a0 = fmaf(q0[k], wk, a0);
                a1 = fmaf(q1[k], wk, a1);
            }
            g_rt16[h][j * BB + lane]      = __float2half_rn(a0);
            g_rt16[h][j * BB + lane + 32] = __float2half_rn(a1);
        }
    }
}

// ---------------------------------------------------------------------------
// Exclusive scan of g_hist into g_cursor (3 small kernels).
// ---------------------------------------------------------------------------
__global__ void __launch_bounds__(1024)
csr_scan1() {
    __shared__ unsigned s[1024];
    const int tid = threadIdx.x;
    const int i0  = blockIdx.x * SCAN_BLOCK + 2 * tid;
    const unsigned a = (i0     < N_E) ? g_hist[i0]     : 0u;
    const unsigned b = (i0 + 1 < N_E) ? g_hist[i0 + 1] : 0u;
    s[tid] = a + b;
    __syncthreads();
    for (int off = 1; off < 1024; off <<= 1) {
        const unsigned v = s[tid];
        const unsigned u = (tid >= off) ? s[tid - off] : 0u;
        __syncthreads();
        s[tid] = v + u;
        __syncthreads();
    }
    const unsigned incl = s[tid];
    const unsigned excl = incl - (a + b);
    if (i0     < N_E) g_cursor[i0]     = excl;        // partial excl scan
    if (i0 + 1 < N_E) g_cursor[i0 + 1] = excl + a;
    if (tid == 1023) g_bsum[blockIdx.x] = incl;
}

__global__ void __launch_bounds__(128)
csr_scan2() {
    __shared__ unsigned s[128];
    const int tid = threadIdx.x;
    const unsigned v0 = (tid < SCAN_NBLK) ? g_bsum[tid] : 0u;
    s[tid] = v0;
    __syncthreads();
    for (int off = 1; off < 128; off <<= 1) {
        const unsigned v = s[tid];
        const unsigned u = (tid >= off) ? s[tid - off] : 0u;
        __syncthreads();
        s[tid] = v + u;
        __syncthreads();
    }
    if (tid < SCAN_NBLK) g_boff[tid] = s[tid] - v0;
}

__global__ void csr_scan3() {
    const int i = blockIdx.x * blockDim.x + threadIdx.x;
    if (i < N_E) g_cursor[i] += g_boff[i / SCAN_BLOCK];
}

// ---------------------------------------------------------------------------
// Slot scatter: 4 triples per thread (int4 index loads, MLP 4).
// ---------------------------------------------------------------------------
__global__ void csr_scatter(const int* __restrict__ subj,
                            const int* __restrict__ rel,
                            const int* __restrict__ obj) {
    const int i  = blockIdx.x * blockDim.x + threadIdx.x;
    const int t0 = i * 4;
    if (t0 >= N_T) return;
    const int4 s4 = __ldg(reinterpret_cast<const int4*>(subj + t0));
    const int4 r4 = __ldg(reinterpret_cast<const int4*>(rel  + t0));
    const int4 o4 = __ldg(reinterpret_cast<const int4*>(obj  + t0));

    unsigned sl0 = atomicAdd(&g_cursor[o4.x], 1u);
    unsigned sl1 = atomicAdd(&g_cursor[o4.y], 1u);
    unsigned sl2 = atomicAdd(&g_cursor[o4.z], 1u);
    unsigned sl3 = atomicAdd(&g_cursor[o4.w], 1u);

    g_sp[sl0] = make_uint2(((unsigned)s4.x << 8) | (unsigned)r4.x, (unsigned)o4.x);
    g_sp[sl1] = make_uint2(((unsigned)s4.y << 8) | (unsigned)r4.y, (unsigned)o4.y);
    g_sp[sl2] = make_uint2(((unsigned)s4.z << 8) | (unsigned)r4.z, (unsigned)o4.z);
    g_sp[sl3] = make_uint2(((unsigned)s4.w << 8) | (unsigned)r4.w, (unsigned)o4.w);
}

// ---------------------------------------------------------------------------
// One hop, strip form: thread = (strip of 8 sorted triples) x (4-batch chunk).
// Prefetch 8 x-gathers + 8 rt rows (MLP 16), fp32 accumulate, emit a vector
// red only at run boundaries (~2.4 per strip instead of 8).
// ---------------------------------------------------------------------------
__device__ __forceinline__ void red_v4(float* dst, float4 m) {
    asm volatile("red.global.add.v4.f32 [%0], {%1,%2,%3,%4};"
                 :: "l"(dst), "f"(m.x), "f"(m.y), "f"(m.z), "f"(m.w)
                 : "memory");
}

__device__ __forceinline__ uint4 ldcs_uint4(const void* p) {
    uint4 v;
    asm volatile("ld.global.cs.v4.u32 {%0,%1,%2,%3}, [%4];"
                 : "=r"(v.x), "=r"(v.y), "=r"(v.z), "=r"(v.w) : "l"(p));
    return v;
}

__global__ void __launch_bounds__(256, 3)
hop_strip(int hop, const int* __restrict__ n_hop) {
    if (hop >= *n_hop) return;
    const int tid = blockIdx.x * 256 + threadIdx.x;
    const int s   = tid >> 4;                 // strip index
    if (s >= N_T / STRIP) return;
    const int c   = tid & 15;                 // chunk: 4 batch elems (8B fp16)
    const int t0  = s * STRIP;

    const __half* __restrict__ xt = g_x16;
    const __half* __restrict__ rt = g_rt16[hop];

    const uint4 a0 = ldcs_uint4(&g_sp[t0]);
    const uint4 a1 = ldcs_uint4(&g_sp[t0 + 2]);
    const uint4 a2 = ldcs_uint4(&g_sp[t0 + 4]);
    const uint4 a3 = ldcs_uint4(&g_sp[t0 + 6]);
    unsigned pk[STRIP] = {a0.x, a0.z, a1.x, a1.z, a2.x, a2.z, a3.x, a3.z};
    unsigned ob[STRIP] = {a0.y, a0.w, a1.y, a1.w, a2.y, a2.w, a3.y, a3.w};

    h4 xv[STRIP], rv[STRIP];
#pragma unroll
    for (int j = 0; j < STRIP; ++j)
        xv[j] = reinterpret_cast<const h4*>(xt + (size_t)(pk[j] >> 8) * BB)[c];
#pragma unroll
    for (int j = 0; j < STRIP; ++j)
        rv[j] = reinterpret_cast<const h4*>(rt + (pk[j] & 255u) * BB)[c];

    float4 acc = make_float4(0.f, 0.f, 0.f, 0.f);
#pragma unroll
    for (int j = 0; j < STRIP; ++j) {
        const float2 xl = __half22float2(xv[j].a), xh = __half22float2(xv[j].b);
        const float2 rl = __half22float2(rv[j].a), rh = __half22float2(rv[j].b);
        acc.x = fmaf(xl.x, rl.x, acc.x);
        acc.y = fmaf(xl.y, rl.y, acc.y);
        acc.z = fmaf(xh.x, rh.x, acc.z);
        acc.w = fmaf(xh.y, rh.y, acc.w);
        const bool emit = (j == STRIP - 1) || (ob[j] != ob[j + 1]);
        if (emit) {
            red_v4(g_y32 + (size_t)ob[j] * BB + c * 4, acc);
            acc = make_float4(0.f, 0.f, 0.f, 0.f);
        }
    }
}

// ---------------------------------------------------------------------------
// Between hops: x16 = fp16(y32); y32 = 0. Guarded on hop+1 < n_hop.
// ---------------------------------------------------------------------------
__global__ void __launch_bounds__(256)
convert_zero(int hop, const int* __restrict__ n_hop) {
    if (hop + 1 >= *n_hop) return;
    const size_t i = (size_t)blockIdx.x * blockDim.x + threadIdx.x;
    float4* __restrict__ y4 = reinterpret_cast<float4*>(g_y32);
    const float4 v = y4[i];
    h4 o;
    o.a = __floats2half2_rn(v.x, v.y);
    o.b = __floats2half2_rn(v.z, v.w);
    reinterpret_cast<h4*>(g_x16)[i] = o;
    y4[i] = make_float4(0.f, 0.f, 0.f, 0.f);
}

// ---------------------------------------------------------------------------
// Final transpose g_y32 (N_E,64) -> out (B,N_E); if n_hop==0, out = x.
// ---------------------------------------------------------------------------
__global__ void transpose_out(float* __restrict__ out,
                              const float* __restrict__ x,
                              const int* __restrict__ n_hop) {
    __shared__ float tile[32][BB + 1];
    const int tid = threadIdx.x;

    if (*n_hop == 0) {   // identity: copy x -> out
        const size_t n = (size_t)BB * N_E;
        const size_t stride = (size_t)gridDim.x * blockDim.x;
        for (size_t i = (size_t)blockIdx.x * blockDim.x + tid; i < n; i += stride)
            out[i] = x[i];
        return;
    }

    const int e0 = blockIdx.x * 32;
    const int f4 = tid & 15;
    for (int er = tid >> 4; er < 32; er += 16) {
        const int e = e0 + er;
        float4 v = make_float4(0.f, 0.f, 0.f, 0.f);
        if (e < N_E)
            v = reinterpret_cast<const float4*>(&g_y32[(size_t)e * BB])[f4];
        tile[er][f4 * 4 + 0] = v.x;
        tile[er][f4 * 4 + 1] = v.y;
        tile[er][f4 * 4 + 2] = v.z;
        tile[er][f4 * 4 + 3] = v.w;
    }
    __syncthreads();

    const int lane = tid & 31;
    const int warp = tid >> 5;
    for (int b = warp; b < BB; b += 8) {
        const int e = e0 + lane;
        if (e < N_E) out[(size_t)b * N_E + e] = tile[lane][b];
    }
}

// ---------------------------------------------------------------------------
// Launch
// ---------------------------------------------------------------------------
extern "C" void kernel_launch(void* const* d_in, const int* in_sizes, int n_in,
                              void* d_out, int out_size) {
    const float* x    = (const float*)d_in[0];
    const float* q    = (const float*)d_in[1];
    const float* W1   = (const float*)d_in[2];
    const float* b1   = (const float*)d_in[3];
    const float* W2   = (const float*)d_in[4];
    const float* b2   = (const float*)d_in[5];
    const float* W3   = (const float*)d_in[6];
    const float* b3   = (const float*)d_in[7];
    const int*   subj = (const int*)d_in[8];
    const int*   rel  = (const int*)d_in[9];
    const int*   obj  = (const int*)d_in[10];
    const int*   nhop = (const int*)d_in[11];
    float*       out  = (float*)d_out;

    csr_zero_hist<<<(N_E + 255) / 256, 256>>>();
    fusedA<<<FUSEA_BLKS, 256>>>(x, q, W1, b1, W2, b2, W3, b3, obj);

    csr_scan1<<<SCAN_NBLK, 1024>>>();
    csr_scan2<<<1, 128>>>();
    csr_scan3<<<(N_E + 255) / 256, 256>>>();
    csr_scatter<<<(N_T / 4 + 255) / 256, 256>>>(subj, rel, obj);

    const int hop_threads = (N_T / STRIP) * 16;       // 2M
    const int hop_blocks  = (hop_threads + 255) / 256;
    const int cv_blocks   = (N_E * BB / 4 + 255) / 256;

    for (int h = 0; h < 3; ++h) {
        hop_strip<<<hop_blocks, 256>>>(h, nhop);
        convert_zero<<<cv_blocks, 256>>>(h, nhop);    // no-op for last hop
    }

    transpose_out<<<TB_TILES, 256>>>(out, x, nhop);
}

// round 15
// speedup vs baseline: 1.2633x; 1.2633x over previous
#include <cuda_runtime.h>
#include <cuda_fp16.h>
#include <cstdint>

#define N_E   200000
#define N_T   1000000
#define N_R   200
#define N_W2V 300
#define BB    64        // batch
#define STRIP 8         // triples per thread-strip

// fp16 gather-side state: (N_E, 64) halves, 128B rows. 25.6 MB.
__device__ __align__(256) __half g_x16[(size_t)N_E * BB];
// fp32 accumulator state: (N_E, 64) floats, 256B rows. 51.2 MB. Pre-zeroed.
__device__ __align__(256) float  g_y32[(size_t)N_E * BB];
// Precomputed r for all 3 hops, relation-major fp16: rt[h][j][b]
__device__ __align__(256) __half g_rt16[3][N_R * BB];

// CSR-sort scratch, rebuilt every call.
#define SCAN_BLOCK 2048
#define SCAN_NBLK  ((N_E + SCAN_BLOCK - 1) / SCAN_BLOCK)   // 98
__device__ unsigned g_hist[N_E];
__device__ unsigned g_cursor[N_E];
__device__ unsigned g_bsum[SCAN_NBLK];
// Sorted-by-obj triple stream: .x = (subj<<8)|rel (26 bits), .y = obj. 8 MB.
__device__ __align__(16) uint2 g_sp[N_T];

struct __align__(8) h4 { __half2 a, b; };   // 4 halves = 8 bytes

// ---------------------------------------------------------------------------
// Transpose x (B, N_E) f32 -> g_x16 (N_E, 64) fp16, zero g_y32, zero g_hist.
// ---------------------------------------------------------------------------
__global__ void transpose_in(const float* __restrict__ x) {
    __shared__ float tile[32][BB + 1];
    const int e0   = blockIdx.x * 32;
    const int tid  = threadIdx.x;          // 256 threads
    const int lane = tid & 31;
    const int warp = tid >> 5;

    for (int b = warp; b < BB; b += 8) {
        const int e = e0 + lane;
        tile[lane][b] = (e < N_E) ? x[(size_t)b * N_E + e] : 0.f;
    }
    // Zero my slice of g_y32 (6250 blocks * 512 float4 = N_E*BB floats) and
    // my 32 histogram bins, while tile loads are in flight.
    {
        float4* __restrict__ y4 = reinterpret_cast<float4*>(g_y32);
        const size_t base = (size_t)blockIdx.x * 512 + tid;
        const float4 z = make_float4(0.f, 0.f, 0.f, 0.f);
        y4[base]       = z;
        y4[base + 256] = z;
        if (tid < 32 && e0 + tid < N_E) g_hist[e0 + tid] = 0u;
    }
    __syncthreads();

    const int l16 = tid & 15;
    for (int er = tid >> 4; er < 32; er += 16) {
        const int e = e0 + er;
        if (e < N_E) {
            h4 v;
            v.a = __floats2half2_rn(tile[er][l16 * 4 + 0], tile[er][l16 * 4 + 1]);
            v.b = __floats2half2_rn(tile[er][l16 * 4 + 2], tile[er][l16 * 4 + 3]);
            reinterpret_cast<h4*>(g_x16 + (size_t)e * BB)[l16] = v;
        }
    }
}

// ---------------------------------------------------------------------------
// r_h = q @ W_h + b_h for all 3 hops at once, stored fp16.
// ---------------------------------------------------------------------------
__global__ void compute_r(const float* __restrict__ q,
                          const float* __restrict__ W1, const float* __restrict__ b1,
                          const float* __restrict__ W2, const float* __restrict__ b2,
                          const float* __restrict__ W3, const float* __restrict__ b3) {
    const int h = blockIdx.x / N_R;
    const int j = blockIdx.x - h * N_R;
    const float* __restrict__ W  = (h == 0) ? W1 : (h == 1) ? W2 : W3;
    const float* __restrict__ bv = (h == 0) ? b1 : (h == 1) ? b2 : b3;

    __shared__ float Wc[N_W2V];
    const int i = threadIdx.x;                     // 0..63 (batch row)
    for (int k = i; k < N_W2V; k += 64)
        Wc[k] = W[(size_t)k * N_R + j];
    __syncthreads();

    float acc = bv[j];
    const float* __restrict__ qi = q + (size_t)i * N_W2V;
#pragma unroll 4
    for (int k = 0; k < N_W2V; ++k)
        acc = fmaf(qi[k], Wc[k], acc);
    g_rt16[h][j * BB + i] = __float2half_rn(acc);
}

// ---------------------------------------------------------------------------
// Histogram of obj: 4 triples per thread (int4 load, MLP 4).
// ---------------------------------------------------------------------------
__global__ void csr_count(const int* __restrict__ obj) {
    const int i  = blockIdx.x * blockDim.x + threadIdx.x;
    const int t0 = i * 4;
    if (t0 >= N_T) return;
    const int4 o4 = __ldg(reinterpret_cast<const int4*>(obj + t0));
    atomicAdd(&g_hist[o4.x], 1u);
    atomicAdd(&g_hist[o4.y], 1u);
    atomicAdd(&g_hist[o4.z], 1u);
    atomicAdd(&g_hist[o4.w], 1u);
}

// ---------------------------------------------------------------------------
// Scan stage 1: per-2048-entity exclusive scan; block sums to g_bsum.
// ---------------------------------------------------------------------------
__global__ void __launch_bounds__(1024)
csr_scan1() {
    __shared__ unsigned s[1024];
    const int tid = threadIdx.x;
    const int i0  = blockIdx.x * SCAN_BLOCK + 2 * tid;
    const unsigned a = (i0     < N_E) ? g_hist[i0]     : 0u;
    const unsigned b = (i0 + 1 < N_E) ? g_hist[i0 + 1] : 0u;
    s[tid] = a + b;
    __syncthreads();
    for (int off = 1; off < 1024; off <<= 1) {
        const unsigned v = s[tid];
        const unsigned u = (tid >= off) ? s[tid - off] : 0u;
        __syncthreads();
        s[tid] = v + u;
        __syncthreads();
    }
    const unsigned incl = s[tid];
    const unsigned excl = incl - (a + b);
    if (i0     < N_E) g_cursor[i0]     = excl;        // partial excl scan
    if (i0 + 1 < N_E) g_cursor[i0 + 1] = excl + a;
    if (tid == 1023) g_bsum[blockIdx.x] = incl;
}

// ---------------------------------------------------------------------------
// Scan stages 2+3 fused: each 256-entity block reduces the bsum prefix it
// needs (<= 98 values) in smem, then adds it to its cursors.
// ---------------------------------------------------------------------------
__global__ void __launch_bounds__(256)
csr_scan23() {
    __shared__ unsigned s[128];
    const int tid = threadIdx.x;
    const int k   = blockIdx.x >> 3;   // which 2048-entity region (256*8)
    if (tid < 128) s[tid] = (tid < k && tid < SCAN_NBLK) ? g_bsum[tid] : 0u;
    __syncthreads();
    for (int off = 64; off > 0; off >>= 1) {
        if (tid < off) s[tid] += s[tid + off];
        __syncthreads();
    }
    const unsigned pref = s[0];
    const int i = blockIdx.x * 256 + tid;
    if (i < N_E) g_cursor[i] += pref;
}

// ---------------------------------------------------------------------------
// Slot scatter: 4 triples per thread (int4 index loads, MLP 4).
// ---------------------------------------------------------------------------
__global__ void csr_scatter(const int* __restrict__ subj,
                            const int* __restrict__ rel,
                            const int* __restrict__ obj) {
    const int i  = blockIdx.x * blockDim.x + threadIdx.x;
    const int t0 = i * 4;
    if (t0 >= N_T) return;
    const int4 s4 = __ldg(reinterpret_cast<const int4*>(subj + t0));
    const int4 r4 = __ldg(reinterpret_cast<const int4*>(rel  + t0));
    const int4 o4 = __ldg(reinterpret_cast<const int4*>(obj  + t0));

    const unsigned sl0 = atomicAdd(&g_cursor[o4.x], 1u);
    const unsigned sl1 = atomicAdd(&g_cursor[o4.y], 1u);
    const unsigned sl2 = atomicAdd(&g_cursor[o4.z], 1u);
    const unsigned sl3 = atomicAdd(&g_cursor[o4.w], 1u);

    g_sp[sl0] = make_uint2(((unsigned)s4.x << 8) | (unsigned)r4.x, (unsigned)o4.x);
    g_sp[sl1] = make_uint2(((unsigned)s4.y << 8) | (unsigned)r4.y, (unsigned)o4.y);
    g_sp[sl2] = make_uint2(((unsigned)s4.z << 8) | (unsigned)r4.z, (unsigned)o4.z);
    g_sp[sl3] = make_uint2(((unsigned)s4.w << 8) | (unsigned)r4.w, (unsigned)o4.w);
}

// ---------------------------------------------------------------------------
// One hop, strip form: thread = (strip of 8 sorted triples) x (4-batch chunk).
// Prefetch 8 x-gathers + 8 rt rows (MLP 16), fp32 accumulate, emit a vector
// red only at run boundaries (~2.4 per strip instead of 8).
// ---------------------------------------------------------------------------
__device__ __forceinline__ void red_v4(float* dst, float4 m) {
    asm volatile("red.global.add.v4.f32 [%0], {%1,%2,%3,%4};"
                 :: "l"(dst), "f"(m.x), "f"(m.y), "f"(m.z), "f"(m.w)
                 : "memory");
}

__device__ __forceinline__ uint4 ldcs_uint4(const void* p) {
    uint4 v;
    asm volatile("ld.global.cs.v4.u32 {%0,%1,%2,%3}, [%4];"
                 : "=r"(v.x), "=r"(v.y), "=r"(v.z), "=r"(v.w) : "l"(p));
    return v;
}

__global__ void __launch_bounds__(256, 3)
hop_strip(int hop, const int* __restrict__ n_hop) {
    if (hop >= *n_hop) return;
    const int tid = blockIdx.x * 256 + threadIdx.x;
    const int s   = tid >> 4;                 // strip index
    if (s >= N_T / STRIP) return;
    const int c   = tid & 15;                 // chunk: 4 batch elems (8B fp16)
    const int t0  = s * STRIP;

    const __half* __restrict__ xt = g_x16;
    const __half* __restrict__ rt = g_rt16[hop];

    const uint4 a0 = ldcs_uint4(&g_sp[t0]);
    const uint4 a1 = ldcs_uint4(&g_sp[t0 + 2]);
    const uint4 a2 = ldcs_uint4(&g_sp[t0 + 4]);
    const uint4 a3 = ldcs_uint4(&g_sp[t0 + 6]);
    unsigned pk[STRIP] = {a0.x, a0.z, a1.x, a1.z, a2.x, a2.z, a3.x, a3.z};
    unsigned ob[STRIP] = {a0.y, a0.w, a1.y, a1.w, a2.y, a2.w, a3.y, a3.w};

    h4 xv[STRIP], rv[STRIP];
#pragma unroll
    for (int j = 0; j < STRIP; ++j)
        xv[j] = reinterpret_cast<const h4*>(xt + (size_t)(pk[j] >> 8) * BB)[c];
#pragma unroll
    for (int j = 0; j < STRIP; ++j)
        rv[j] = reinterpret_cast<const h4*>(rt + (pk[j] & 255u) * BB)[c];

    float4 acc = make_float4(0.f, 0.f, 0.f, 0.f);
#pragma unroll
    for (int j = 0; j < STRIP; ++j) {
        const float2 xl = __half22float2(xv[j].a), xh = __half22float2(xv[j].b);
        const float2 rl = __half22float2(rv[j].a), rh = __half22float2(rv[j].b);
        acc.x = fmaf(xl.x, rl.x, acc.x);
        acc.y = fmaf(xl.y, rl.y, acc.y);
        acc.z = fmaf(xh.x, rh.x, acc.z);
        acc.w = fmaf(xh.y, rh.y, acc.w);
        const bool emit = (j == STRIP - 1) || (ob[j] != ob[j + 1]);
        if (emit) {
            red_v4(g_y32 + (size_t)ob[j] * BB + c * 4, acc);
            acc = make_float4(0.f, 0.f, 0.f, 0.f);
        }
    }
}

// ---------------------------------------------------------------------------
// Between hops: x16 = fp16(y32); y32 = 0. Guarded on hop+1 < n_hop.
// ---------------------------------------------------------------------------
__global__ void __launch_bounds__(256)
convert_zero(int hop, const int* __restrict__ n_hop) {
    if (hop + 1 >= *n_hop) return;
    const size_t i = (size_t)blockIdx.x * blockDim.x + threadIdx.x;
    float4* __restrict__ y4 = reinterpret_cast<float4*>(g_y32);
    const float4 v = y4[i];
    h4 o;
    o.a = __floats2half2_rn(v.x, v.y);
    o.b = __floats2half2_rn(v.z, v.w);
    reinterpret_cast<h4*>(g_x16)[i] = o;
    y4[i] = make_float4(0.f, 0.f, 0.f, 0.f);
}

// ---------------------------------------------------------------------------
// Final transpose g_y32 (N_E,64) -> out (B,N_E); if n_hop==0, out = x.
// ---------------------------------------------------------------------------
__global__ void transpose_out(float* __restrict__ out,
                              const float* __restrict__ x,
                              const int* __restrict__ n_hop) {
    __shared__ float tile[32][BB + 1];
    const int tid = threadIdx.x;

    if (*n_hop == 0) {   // identity: copy x -> out
        const size_t n = (size_t)BB * N_E;
        const size_t stride = (size_t)gridDim.x * blockDim.x;
        for (size_t i = (size_t)blockIdx.x * blockDim.x + tid; i < n; i += stride)
            out[i] = x[i];
        return;
    }

    const int e0 = blockIdx.x * 32;
    const int f4 = tid & 15;
    for (int er = tid >> 4; er < 32; er += 16) {
        const int e = e0 + er;
        float4 v = make_float4(0.f, 0.f, 0.f, 0.f);
        if (e < N_E)
            v = reinterpret_cast<const float4*>(&g_y32[(size_t)e * BB])[f4];
        tile[er][f4 * 4 + 0] = v.x;
        tile[er][f4 * 4 + 1] = v.y;
        tile[er][f4 * 4 + 2] = v.z;
        tile[er][f4 * 4 + 3] = v.w;
    }
    __syncthreads();

    const int lane = tid & 31;
    const int warp = tid >> 5;
    for (int b = warp; b < BB; b += 8) {
        const int e = e0 + lane;
        if (e < N_E) out[(size_t)b * N_E + e] = tile[lane][b];
    }
}

// ---------------------------------------------------------------------------
// Launch
// ---------------------------------------------------------------------------
extern "C" void kernel_launch(void* const* d_in, const int* in_sizes, int n_in,
                              void* d_out, int out_size) {
    const float* x    = (const float*)d_in[0];
    const float* q    = (const float*)d_in[1];
    const float* W1   = (const float*)d_in[2];
    const float* b1   = (const float*)d_in[3];
    const float* W2   = (const float*)d_in[4];
    const float* b2   = (const float*)d_in[5];
    const float* W3   = (const float*)d_in[6];
    const float* b3   = (const float*)d_in[7];
    const int*   subj = (const int*)d_in[8];
    const int*   rel  = (const int*)d_in[9];
    const int*   obj  = (const int*)d_in[10];
    const int*   nhop = (const int*)d_in[11];
    float*       out  = (float*)d_out;

    const int tb = (N_E + 31) / 32;                   // 6250

    transpose_in<<<tb, 256>>>(x);                     // + zero y32 + zero hist
    compute_r<<<3 * N_R, 64>>>(q, W1, b1, W2, b2, W3, b3);

    csr_count<<<(N_T / 4 + 255) / 256, 256>>>(obj);
    csr_scan1<<<SCAN_NBLK, 1024>>>();
    csr_scan23<<<(N_E + 255) / 256, 256>>>();
    csr_scatter<<<(N_T / 4 + 255) / 256, 256>>>(subj, rel, obj);

    const int hop_threads = (N_T / STRIP) * 16;       // 2M
    const int hop_blocks  = (hop_threads + 255) / 256;
    const int cv_blocks   = (N_E * BB / 4 + 255) / 256;

    for (int h = 0; h < 3; ++h) {
        hop_strip<<<hop_blocks, 256>>>(h, nhop);
        convert_zero<<<cv_blocks, 256>>>(h, nhop);    // no-op for last hop
    }

    transpose_out<<<tb, 256>>>(out, x, nhop);
}